// round 7
// baseline (speedup 1.0000x reference)
#include <cuda_runtime.h>
#include <cuda_bf16.h>

// x: (128,1,32768) fp32, 17 fixed filters baked as constants, out: (128,17,32768) = relu(conv same), PAD_LO=47.
// Filters 0..5 alternating even-neg K={2,4,8,16,32,64}; 6..11 odd-neg (negation); 12..16 piecewise-quadratic
// bumps len 1.5K, K=4..64.
//
// R7 = R2's proven structure at 8 outputs/thread (NTHR=128, TILE=1024): amortizes LDS/scan/indexing
// overhead (280 -> 231 issue slots per output) while keeping the quad filters as pure FFMA-imm
// (z-factorization is closed: it trades cheap FFMA for expensive L1 traffic, +31k stall cyc/SM).
// __launch_bounds__(128,7): 7 blocks/SM -> 3.95 waves (98.8% schedule efficiency).

#define NB    128
#define LSEQ  32768
#define NFILT 17
#define TILE  1024
#define NTHR  128
#define NSV   1119          // valid xs elements = TILE + 95
#define NSX   1120
#define CHUNK 9             // scan elements per thread: 128*9 = 1152 >= 1119

__device__ __forceinline__ float triWeightAbs(int t, int c) {
    // weight of quad filter t (t=0..4 <-> K=4,8,16,32,64) at absolute tap c (0..95); 0 outside support
    const int Ks[5] = {4, 8, 16, 32, 64};
    int K = Ks[t];
    int Lf = K + K / 2;
    int o = 47 - (Lf - 1) / 2;
    int j = c - o;
    if (j < 0 || j >= Lf) return 0.0f;
    int q = K / 4, half = K / 2;
    int s = j / half;
    int u = j - s * half;
    int num = (u < q) ? (u + 1) : (half - u);
    float b = (float)num / (float)q;        // exact: power-of-two denominator
    float w = b * b;
    return (s == 1) ? 2.0f * w : -w;
}

__global__ __launch_bounds__(NTHR, 7)
void Hybrid_block_64175401337035_kernel(const float* __restrict__ x,
                                        float* __restrict__ y) {
    __shared__ __align__(16) float xs[NSX];
    __shared__ __align__(16) float E[NSX];   // E[p] = (-1)^p * sum_{q<p} (-1)^q xs[q]; E[0]=0
    __shared__ float warpAgg[4];

    const int tid = threadIdx.x;
    const int n = blockIdx.y;
    const int tileStart = blockIdx.x * TILE;
    const float* xg = x + (size_t)n * LSEQ;

    // ---- load input tile (zero-padded at sequence edges) ----
    #pragma unroll
    for (int q = tid; q < NSX; q += NTHR) {
        int g = tileStart - 47 + q;
        xs[q] = (q < NSV && g >= 0 && g < LSEQ) ? xg[g] : 0.0f;
    }
    __syncthreads();

    // ---- block scan of (-1)^q xs[q], CHUNK elems/thread ----
    float loc[CHUNK];
    float run = 0.0f;
    const int qb = tid * CHUNK;
    #pragma unroll
    for (int j = 0; j < CHUNK; ++j) {
        int q = qb + j;
        float v = 0.0f;
        if (q < NSV) { v = xs[q]; if (q & 1) v = -v; }
        run += v;
        loc[j] = run;
    }
    const unsigned lane = tid & 31;
    const unsigned wid = tid >> 5;
    float inc = run;
    #pragma unroll
    for (int o = 1; o < 32; o <<= 1) {
        float nb = __shfl_up_sync(0xffffffffu, inc, o);
        if (lane >= (unsigned)o) inc += nb;
    }
    if (lane == 31) warpAgg[wid] = inc;
    __syncthreads();
    if (tid < 4) {
        float wv = warpAgg[tid];
        #pragma unroll
        for (int o = 1; o < 4; o <<= 1) {
            float nb = __shfl_up_sync(0xFu, wv, o);
            if (tid >= o) wv += nb;
        }
        warpAgg[tid] = wv;
    }
    __syncthreads();
    float pre = inc - run;
    if (wid > 0) pre += warpAgg[wid - 1];
    if (tid == 0) E[0] = 0.0f;
    #pragma unroll
    for (int j = 0; j < CHUNK; ++j) {
        int q = qb + j;
        if (q < NSV) {
            float v = pre + loc[j];
            E[q + 1] = (q & 1) ? v : -v;   // E[q+1] = (-1)^(q+1) * A[q+1]
        }
    }
    __syncthreads();

    const int xl0 = tid * 8;                 // 8 consecutive outputs per thread
    float* ybase = y + (size_t)n * NFILT * LSEQ + tileStart + xl0;

    // ---- 12 alternating filters: two 4-wide halves (base xl0, xl0+4), aligned float4 LDS ----
    #pragma unroll
    for (int h = 0; h < 2; ++h) {
        const int bb = xl0 + 4 * h;
        const float4 e16 = *(const float4*)(E + bb + 16);
        const float4 e32 = *(const float4*)(E + bb + 32);
        const float4 e40 = *(const float4*)(E + bb + 40);
        const float4 e44 = *(const float4*)(E + bb + 44);
        const float4 e48 = *(const float4*)(E + bb + 48);
        const float4 e52 = *(const float4*)(E + bb + 52);
        const float4 e56 = *(const float4*)(E + bb + 56);
        const float4 e64 = *(const float4*)(E + bb + 64);
        const float4 e80 = *(const float4*)(E + bb + 80);

        float w0[4], w1[4];
        #define EMIT(kkidx)                                                          \
        {                                                                            \
            float4 ye, yo;                                                           \
            ye.x = fmaxf(w0[0] - w1[0], 0.0f); yo.x = fmaxf(w1[0] - w0[0], 0.0f);    \
            ye.y = fmaxf(w0[1] - w1[1], 0.0f); yo.y = fmaxf(w1[1] - w0[1], 0.0f);    \
            ye.z = fmaxf(w0[2] - w1[2], 0.0f); yo.z = fmaxf(w1[2] - w0[2], 0.0f);    \
            ye.w = fmaxf(w0[3] - w1[3], 0.0f); yo.w = fmaxf(w1[3] - w0[3], 0.0f);    \
            *(float4*)(ybase + (size_t)(kkidx) * LSEQ + 4 * h) = ye;                 \
            *(float4*)(ybase + (size_t)(6 + (kkidx)) * LSEQ + 4 * h) = yo;           \
        }
        // K=2, o=47
        w0[0]=e44.w; w0[1]=e48.x; w0[2]=e48.y; w0[3]=e48.z;
        w1[0]=e48.y; w1[1]=e48.z; w1[2]=e48.w; w1[3]=e52.x;
        EMIT(0)
        // K=4, o=46
        w0[0]=e44.z; w0[1]=e44.w; w0[2]=e48.x; w0[3]=e48.y;
        w1[0]=e48.z; w1[1]=e48.w; w1[2]=e52.x; w1[3]=e52.y;
        EMIT(1)
        // K=8, o=44
        w0[0]=e44.x; w0[1]=e44.y; w0[2]=e44.z; w0[3]=e44.w;
        w1[0]=e52.x; w1[1]=e52.y; w1[2]=e52.z; w1[3]=e52.w;
        EMIT(2)
        // K=16, o=40
        w0[0]=e40.x; w0[1]=e40.y; w0[2]=e40.z; w0[3]=e40.w;
        w1[0]=e56.x; w1[1]=e56.y; w1[2]=e56.z; w1[3]=e56.w;
        EMIT(3)
        // K=32, o=32
        w0[0]=e32.x; w0[1]=e32.y; w0[2]=e32.z; w0[3]=e32.w;
        w1[0]=e64.x; w1[1]=e64.y; w1[2]=e64.z; w1[3]=e64.w;
        EMIT(4)
        // K=64, o=16
        w0[0]=e16.x; w0[1]=e16.y; w0[2]=e16.z; w0[3]=e16.w;
        w1[0]=e80.x; w1[1]=e80.y; w1[2]=e80.z; w1[3]=e80.w;
        EMIT(5)
        #undef EMIT
    }

    // ---- 5 quadratic filters: fully-unrolled FFMA-imm sweep over 8 outputs ----
    float acc[5][8];
    #pragma unroll
    for (int t = 0; t < 5; ++t)
        #pragma unroll
        for (int pp = 0; pp < 8; ++pp) acc[t][pp] = 0.0f;

    float4 wa = *(const float4*)(xs + xl0);
    float4 wb = *(const float4*)(xs + xl0 + 4);
    #pragma unroll
    for (int m = 0; m < 24; ++m) {
        float4 wc = *(const float4*)(xs + xl0 + 8 + 4 * m);
        float win[12] = {wa.x, wa.y, wa.z, wa.w, wb.x, wb.y, wb.z, wb.w,
                         wc.x, wc.y, wc.z, wc.w};
        #pragma unroll
        for (int d = 0; d < 4; ++d) {
            const int c = 4 * m + d;
            #pragma unroll
            for (int t = 0; t < 5; ++t) {
                const float w = triWeightAbs(t, c);
                if (w != 0.0f) {
                    #pragma unroll
                    for (int pp = 0; pp < 8; ++pp)
                        acc[t][pp] = fmaf(w, win[d + pp], acc[t][pp]);
                }
            }
        }
        wa = wb; wb = wc;
    }
    #pragma unroll
    for (int t = 0; t < 5; ++t) {
        float4 v0, v1;
        v0.x = fmaxf(acc[t][0], 0.0f);
        v0.y = fmaxf(acc[t][1], 0.0f);
        v0.z = fmaxf(acc[t][2], 0.0f);
        v0.w = fmaxf(acc[t][3], 0.0f);
        v1.x = fmaxf(acc[t][4], 0.0f);
        v1.y = fmaxf(acc[t][5], 0.0f);
        v1.z = fmaxf(acc[t][6], 0.0f);
        v1.w = fmaxf(acc[t][7], 0.0f);
        *(float4*)(ybase + (size_t)(12 + t) * LSEQ) = v0;
        *(float4*)(ybase + (size_t)(12 + t) * LSEQ + 4) = v1;
    }
}

extern "C" void kernel_launch(void* const* d_in, const int* in_sizes, int n_in,
                              void* d_out, int out_size) {
    const float* x = (const float*)d_in[0];
    float* y = (float*)d_out;
    dim3 grid(LSEQ / TILE, NB);
    Hybrid_block_64175401337035_kernel<<<grid, NTHR>>>(x, y);
}

// round 8
// speedup vs baseline: 1.5770x; 1.5770x over previous
#include <cuda_runtime.h>
#include <cuda_bf16.h>

// x: (128,1,32768) fp32, W: 17 fixed filters (baked as constants), out: (128,17,32768) = relu(conv same)
// PAD_LO=47. Filters 0..5 alternating even-negative K={2,4,8,16,32,64}; 6..11 odd-negative (negation);
// 12..16 piecewise-quadratic bumps, len 1.5K for K=4..64.
//
// R8 = R5 kernel (proven 48.7us) with pure schedule surgery, math identical:
//  - quad FFMA sweep + its 5 store planes moved BEFORE the scan (depends only on xs):
//    spreads the 17-plane STG burst into 5 early + 12 late, and overlaps FFMA with
//    scan shuffle/LDS latency across warps.
//  - all output addressing in 32-bit ints (max offset 70.8M < 2^31): kills IMAD.WIDE chains.
//  - __launch_bounds__(256,7): 3.95 waves, 98.8% schedule efficiency (R5-proven, regs 32).

#define NB    128
#define LSEQ  32768
#define NFILT 17
#define TILE  1024
#define NTHR  256
#define NSV   1119          // valid xs elements = TILE + 95
#define NSX   1120

__device__ __forceinline__ float triWeightAbs(int t, int c) {
    // weight of quad filter t (t=0..4 <-> K=4,8,16,32,64) at absolute tap c (0..95); 0 outside support
    const int Ks[5] = {4, 8, 16, 32, 64};
    int K = Ks[t];
    int Lf = K + K / 2;
    int o = 47 - (Lf - 1) / 2;
    int j = c - o;
    if (j < 0 || j >= Lf) return 0.0f;
    int q = K / 4, half = K / 2;
    int s = j / half;
    int u = j - s * half;
    int num = (u < q) ? (u + 1) : (half - u);
    float b = (float)num / (float)q;        // exact: power-of-two denominator
    float w = b * b;
    return (s == 1) ? 2.0f * w : -w;
}

__global__ __launch_bounds__(NTHR, 7)
void Hybrid_block_64175401337035_kernel(const float* __restrict__ x,
                                        float* __restrict__ y) {
    __shared__ __align__(16) float xs[NSX];
    __shared__ __align__(16) float E[NSX];   // E[p] = (-1)^p * sum_{q<p} (-1)^q xs[q]; E[0]=0
    __shared__ float warpAgg[8];

    const int tid = threadIdx.x;
    const int n = blockIdx.y;
    const int tileStart = blockIdx.x * TILE;
    const float* xg = x + (size_t)n * LSEQ;

    // ---- load input tile (zero-padded at sequence edges); dense, conflict-free ----
    #pragma unroll
    for (int q = tid; q < NSX; q += NTHR) {
        int g = tileStart - 47 + q;
        xs[q] = (q < NSV && g >= 0 && g < LSEQ) ? xg[g] : 0.0f;
    }
    __syncthreads();                                   // sync 1 — xs ready

    const int xl0 = tid * 4;                           // 16B/lane stride: conflict-free LDS.128
    // 32-bit output offsets (max 128*17*32768 = 70.8M elements < 2^31)
    float* ybase = y + (n * (NFILT * LSEQ) + tileStart + xl0);

    // ============ PHASE 1: quad filters (xs only) — FFMA sweep + early stores ============
    {
        float acc[5][4];
        #pragma unroll
        for (int t = 0; t < 5; ++t)
            #pragma unroll
            for (int pp = 0; pp < 4; ++pp) acc[t][pp] = 0.0f;

        float4 cur = *(const float4*)(xs + xl0);
        #pragma unroll
        for (int m = 0; m < 24; ++m) {
            float4 nxt = *(const float4*)(xs + xl0 + 4 * m + 4);
            float win[8] = {cur.x, cur.y, cur.z, cur.w, nxt.x, nxt.y, nxt.z, nxt.w};
            #pragma unroll
            for (int d = 0; d < 4; ++d) {
                const int c = 4 * m + d;
                #pragma unroll
                for (int t = 0; t < 5; ++t) {
                    const float w = triWeightAbs(t, c);
                    if (w != 0.0f) {
                        #pragma unroll
                        for (int pp = 0; pp < 4; ++pp)
                            acc[t][pp] = fmaf(w, win[d + pp], acc[t][pp]);
                    }
                }
            }
            cur = nxt;
        }
        #pragma unroll
        for (int t = 0; t < 5; ++t) {
            float4 v;
            v.x = fmaxf(acc[t][0], 0.0f);
            v.y = fmaxf(acc[t][1], 0.0f);
            v.z = fmaxf(acc[t][2], 0.0f);
            v.w = fmaxf(acc[t][3], 0.0f);
            *(float4*)(ybase + (12 + t) * LSEQ) = v;   // early stores: 5 planes
        }
    }

    // ============ PHASE 2: block scan of (-1)^q xs[q], chunk=5/thread ============
    float loc[5];
    float run = 0.0f;
    const int qb = tid * 5;
    #pragma unroll
    for (int j = 0; j < 5; ++j) {
        int q = qb + j;
        float v = 0.0f;
        if (q < NSV) { v = xs[q]; if (q & 1) v = -v; }
        run += v;
        loc[j] = run;
    }
    const unsigned lane = tid & 31;
    const unsigned wid = tid >> 5;
    float inc = run;
    #pragma unroll
    for (int o = 1; o < 32; o <<= 1) {
        float nb = __shfl_up_sync(0xffffffffu, inc, o);
        if (lane >= (unsigned)o) inc += nb;
    }
    if (lane == 31) warpAgg[wid] = inc;
    __syncthreads();                                   // sync 2
    if (tid < 8) {
        float wv = warpAgg[tid];
        #pragma unroll
        for (int o = 1; o < 8; o <<= 1) {
            float nb = __shfl_up_sync(0xffu, wv, o);
            if (tid >= o) wv += nb;
        }
        warpAgg[tid] = wv;
    }
    __syncthreads();                                   // sync 3
    float pre = inc - run;
    if (wid > 0) pre += warpAgg[wid - 1];
    if (tid == 0) E[0] = 0.0f;
    #pragma unroll
    for (int j = 0; j < 5; ++j) {
        int q = qb + j;
        if (q < NSV) {
            float v = pre + loc[j];
            E[q + 1] = (q & 1) ? v : -v;   // E[q+1] = (-1)^(q+1) * A[q+1]
        }
    }
    __syncthreads();                                   // sync 4 — E ready

    // ============ PHASE 3: 12 alternating filters via aligned E windows + late stores ============
    const float4 e16 = *(const float4*)(E + xl0 + 16);
    const float4 e32 = *(const float4*)(E + xl0 + 32);
    const float4 e40 = *(const float4*)(E + xl0 + 40);
    const float4 e44 = *(const float4*)(E + xl0 + 44);
    const float4 e48 = *(const float4*)(E + xl0 + 48);
    const float4 e52 = *(const float4*)(E + xl0 + 52);
    const float4 e56 = *(const float4*)(E + xl0 + 56);
    const float4 e64 = *(const float4*)(E + xl0 + 64);
    const float4 e80 = *(const float4*)(E + xl0 + 80);

    {
        float w0[4], w1[4];
        #define EMIT(kkidx)                                                          \
        {                                                                            \
            float4 ye, yo;                                                           \
            ye.x = fmaxf(w0[0] - w1[0], 0.0f); yo.x = fmaxf(w1[0] - w0[0], 0.0f);    \
            ye.y = fmaxf(w0[1] - w1[1], 0.0f); yo.y = fmaxf(w1[1] - w0[1], 0.0f);    \
            ye.z = fmaxf(w0[2] - w1[2], 0.0f); yo.z = fmaxf(w1[2] - w0[2], 0.0f);    \
            ye.w = fmaxf(w0[3] - w1[3], 0.0f); yo.w = fmaxf(w1[3] - w0[3], 0.0f);    \
            *(float4*)(ybase + (kkidx) * LSEQ) = ye;                                 \
            *(float4*)(ybase + (6 + (kkidx)) * LSEQ) = yo;                           \
        }
        // K=2, o=47: W0 @47, W1 @49
        w0[0]=e44.w; w0[1]=e48.x; w0[2]=e48.y; w0[3]=e48.z;
        w1[0]=e48.y; w1[1]=e48.z; w1[2]=e48.w; w1[3]=e52.x;
        EMIT(0)
        // K=4, o=46: W0 @46, W1 @50
        w0[0]=e44.z; w0[1]=e44.w; w0[2]=e48.x; w0[3]=e48.y;
        w1[0]=e48.z; w1[1]=e48.w; w1[2]=e52.x; w1[3]=e52.y;
        EMIT(1)
        // K=8, o=44: W0 @44, W1 @52
        w0[0]=e44.x; w0[1]=e44.y; w0[2]=e44.z; w0[3]=e44.w;
        w1[0]=e52.x; w1[1]=e52.y; w1[2]=e52.z; w1[3]=e52.w;
        EMIT(2)
        // K=16, o=40: W0 @40, W1 @56
        w0[0]=e40.x; w0[1]=e40.y; w0[2]=e40.z; w0[3]=e40.w;
        w1[0]=e56.x; w1[1]=e56.y; w1[2]=e56.z; w1[3]=e56.w;
        EMIT(3)
        // K=32, o=32: W0 @32, W1 @64
        w0[0]=e32.x; w0[1]=e32.y; w0[2]=e32.z; w0[3]=e32.w;
        w1[0]=e64.x; w1[1]=e64.y; w1[2]=e64.z; w1[3]=e64.w;
        EMIT(4)
        // K=64, o=16: W0 @16, W1 @80
        w0[0]=e16.x; w0[1]=e16.y; w0[2]=e16.z; w0[3]=e16.w;
        w1[0]=e80.x; w1[1]=e80.y; w1[2]=e80.z; w1[3]=e80.w;
        EMIT(5)
        #undef EMIT
    }
}

extern "C" void kernel_launch(void* const* d_in, const int* in_sizes, int n_in,
                              void* d_out, int out_size) {
    const float* x = (const float*)d_in[0];
    float* y = (float*)d_out;
    dim3 grid(LSEQ / TILE, NB);
    Hybrid_block_64175401337035_kernel<<<grid, NTHR>>>(x, y);
}

// round 9
// speedup vs baseline: 1.6782x; 1.0642x over previous
#include <cuda_runtime.h>
#include <cuda_bf16.h>

// x: (128,1,32768) fp32, W: 17 fixed filters (baked as constants), out: (128,17,32768) = relu(conv same)
// PAD_LO=47. Filters 0..5 alternating even-negative K={2,4,8,16,32,64}; 6..11 odd-negative (negation);
// 12..16 piecewise-quadratic bumps, len 1.5K for K=4..64.
//
// R9 = R2 (best measured: 48.06us ncu) byte-identical EXCEPT all 17 output stores use __stcs
// (streaming / evict-first): output lines are dead-on-arrival in L2, so don't let them churn
// the cache against the read stream. Tests the last store-side knob that doesn't change bytes;
// kernel is otherwise at the ~6.3TB/s LTS-cap floor (302MB / 48us, invariant across 8 variants).

#define NB    128
#define LSEQ  32768
#define NFILT 17
#define TILE  1024
#define NTHR  256
#define NSV   1119          // valid xs elements = TILE + 95
#define NSX   1120

__device__ __forceinline__ float triWeightAbs(int t, int c) {
    // weight of quad filter t (t=0..4 <-> K=4,8,16,32,64) at absolute tap c (0..95); 0 outside support
    const int Ks[5] = {4, 8, 16, 32, 64};
    int K = Ks[t];
    int Lf = K + K / 2;
    int o = 47 - (Lf - 1) / 2;
    int j = c - o;
    if (j < 0 || j >= Lf) return 0.0f;
    int q = K / 4, half = K / 2;
    int s = j / half;
    int u = j - s * half;
    int num = (u < q) ? (u + 1) : (half - u);
    float b = (float)num / (float)q;        // exact: power-of-two denominator
    float w = b * b;
    return (s == 1) ? 2.0f * w : -w;
}

__global__ __launch_bounds__(NTHR)
void Hybrid_block_64175401337035_kernel(const float* __restrict__ x,
                                        float* __restrict__ y) {
    __shared__ __align__(16) float xs[NSX];
    __shared__ __align__(16) float E[NSX];   // E[p] = (-1)^p * sum_{q<p} (-1)^q xs[q]; E[0]=0
    __shared__ float warpAgg[8];

    const int tid = threadIdx.x;
    const int n = blockIdx.y;
    const int tileStart = blockIdx.x * TILE;
    const float* xg = x + (size_t)n * LSEQ;

    // ---- load input tile (zero-padded at sequence edges); dense, conflict-free ----
    #pragma unroll
    for (int q = tid; q < NSX; q += NTHR) {
        int g = tileStart - 47 + q;
        xs[q] = (q < NSV && g >= 0 && g < LSEQ) ? xg[g] : 0.0f;
    }
    __syncthreads();

    // ---- block scan of (-1)^q xs[q], chunk=5/thread; stride-5 reads are conflict-free ----
    float loc[5];
    float run = 0.0f;
    const int qb = tid * 5;
    #pragma unroll
    for (int j = 0; j < 5; ++j) {
        int q = qb + j;
        float v = 0.0f;
        if (q < NSV) { v = xs[q]; if (q & 1) v = -v; }
        run += v;
        loc[j] = run;
    }
    const unsigned lane = tid & 31;
    const unsigned wid = tid >> 5;
    float inc = run;
    #pragma unroll
    for (int o = 1; o < 32; o <<= 1) {
        float nb = __shfl_up_sync(0xffffffffu, inc, o);
        if (lane >= (unsigned)o) inc += nb;
    }
    if (lane == 31) warpAgg[wid] = inc;
    __syncthreads();
    if (tid < 8) {
        float wv = warpAgg[tid];
        #pragma unroll
        for (int o = 1; o < 8; o <<= 1) {
            float nb = __shfl_up_sync(0xffu, wv, o);
            if (tid >= o) wv += nb;
        }
        warpAgg[tid] = wv;
    }
    __syncthreads();
    float pre = inc - run;
    if (wid > 0) pre += warpAgg[wid - 1];
    if (tid == 0) E[0] = 0.0f;
    #pragma unroll
    for (int j = 0; j < 5; ++j) {
        int q = qb + j;
        if (q < NSV) {
            float v = pre + loc[j];
            // E[q+1] = (-1)^(q+1) * A[q+1]:  q even -> negative
            E[q + 1] = (q & 1) ? v : -v;
        }
    }
    __syncthreads();

    const int xl0 = tid * 4;
    const int i0 = tileStart + xl0;
    float* ybase = y + (size_t)n * NFILT * LSEQ + i0;

    // ---- 12 alternating filters: s(a) = E[a+K]-E[a]; all windows served by 9 aligned LDS.128 ----
    const float4 e16 = *(const float4*)(E + xl0 + 16);
    const float4 e32 = *(const float4*)(E + xl0 + 32);
    const float4 e40 = *(const float4*)(E + xl0 + 40);
    const float4 e44 = *(const float4*)(E + xl0 + 44);
    const float4 e48 = *(const float4*)(E + xl0 + 48);
    const float4 e52 = *(const float4*)(E + xl0 + 52);
    const float4 e56 = *(const float4*)(E + xl0 + 56);
    const float4 e64 = *(const float4*)(E + xl0 + 64);
    const float4 e80 = *(const float4*)(E + xl0 + 80);

    {
        float w0[4], w1[4];
        #define EMIT(kkidx)                                                          \
        {                                                                            \
            float4 ye, yo;                                                           \
            ye.x = fmaxf(w0[0] - w1[0], 0.0f); yo.x = fmaxf(w1[0] - w0[0], 0.0f);    \
            ye.y = fmaxf(w0[1] - w1[1], 0.0f); yo.y = fmaxf(w1[1] - w0[1], 0.0f);    \
            ye.z = fmaxf(w0[2] - w1[2], 0.0f); yo.z = fmaxf(w1[2] - w0[2], 0.0f);    \
            ye.w = fmaxf(w0[3] - w1[3], 0.0f); yo.w = fmaxf(w1[3] - w0[3], 0.0f);    \
            __stcs((float4*)(ybase + (size_t)(kkidx) * LSEQ), ye);                   \
            __stcs((float4*)(ybase + (size_t)(6 + (kkidx)) * LSEQ), yo);             \
        }
        // K=2, o=47: W0 @47, W1 @49
        w0[0]=e44.w; w0[1]=e48.x; w0[2]=e48.y; w0[3]=e48.z;
        w1[0]=e48.y; w1[1]=e48.z; w1[2]=e48.w; w1[3]=e52.x;
        EMIT(0)
        // K=4, o=46: W0 @46, W1 @50
        w0[0]=e44.z; w0[1]=e44.w; w0[2]=e48.x; w0[3]=e48.y;
        w1[0]=e48.z; w1[1]=e48.w; w1[2]=e52.x; w1[3]=e52.y;
        EMIT(1)
        // K=8, o=44: W0 @44, W1 @52
        w0[0]=e44.x; w0[1]=e44.y; w0[2]=e44.z; w0[3]=e44.w;
        w1[0]=e52.x; w1[1]=e52.y; w1[2]=e52.z; w1[3]=e52.w;
        EMIT(2)
        // K=16, o=40: W0 @40, W1 @56
        w0[0]=e40.x; w0[1]=e40.y; w0[2]=e40.z; w0[3]=e40.w;
        w1[0]=e56.x; w1[1]=e56.y; w1[2]=e56.z; w1[3]=e56.w;
        EMIT(3)
        // K=32, o=32: W0 @32, W1 @64
        w0[0]=e32.x; w0[1]=e32.y; w0[2]=e32.z; w0[3]=e32.w;
        w1[0]=e64.x; w1[1]=e64.y; w1[2]=e64.z; w1[3]=e64.w;
        EMIT(4)
        // K=64, o=16: W0 @16, W1 @80
        w0[0]=e16.x; w0[1]=e16.y; w0[2]=e16.z; w0[3]=e16.w;
        w1[0]=e80.x; w1[1]=e80.y; w1[2]=e80.z; w1[3]=e80.w;
        EMIT(5)
        #undef EMIT
    }

    // ---- 5 quadratic filters: fully-unrolled sweep, FFMA-imm, dense LDS.128 ----
    float acc[5][4];
    #pragma unroll
    for (int t = 0; t < 5; ++t)
        #pragma unroll
        for (int pp = 0; pp < 4; ++pp) acc[t][pp] = 0.0f;

    float4 cur = *(const float4*)(xs + xl0);
    #pragma unroll
    for (int m = 0; m < 24; ++m) {
        float4 nxt = *(const float4*)(xs + xl0 + 4 * m + 4);
        float win[8] = {cur.x, cur.y, cur.z, cur.w, nxt.x, nxt.y, nxt.z, nxt.w};
        #pragma unroll
        for (int d = 0; d < 4; ++d) {
            const int c = 4 * m + d;
            #pragma unroll
            for (int t = 0; t < 5; ++t) {
                const float w = triWeightAbs(t, c);
                if (w != 0.0f) {
                    #pragma unroll
                    for (int pp = 0; pp < 4; ++pp)
                        acc[t][pp] = fmaf(w, win[d + pp], acc[t][pp]);
                }
            }
        }
        cur = nxt;
    }
    #pragma unroll
    for (int t = 0; t < 5; ++t) {
        float4 v;
        v.x = fmaxf(acc[t][0], 0.0f);
        v.y = fmaxf(acc[t][1], 0.0f);
        v.z = fmaxf(acc[t][2], 0.0f);
        v.w = fmaxf(acc[t][3], 0.0f);
        __stcs((float4*)(ybase + (size_t)(12 + t) * LSEQ), v);
    }
}

extern "C" void kernel_launch(void* const* d_in, const int* in_sizes, int n_in,
                              void* d_out, int out_size) {
    const float* x = (const float*)d_in[0];
    float* y = (float*)d_out;
    dim3 grid(LSEQ / TILE, NB);
    Hybrid_block_64175401337035_kernel<<<grid, NTHR>>>(x, y);
}

// round 10
// speedup vs baseline: 1.7188x; 1.0242x over previous
#include <cuda_runtime.h>
#include <cuda_bf16.h>

// x: (128,1,32768) fp32, W: 17 fixed filters (baked as constants), out: (128,17,32768) = relu(conv same)
// PAD_LO=47. Filters 0..5 alternating even-negative K={2,4,8,16,32,64}; 6..11 odd-negative (negation);
// 12..16 piecewise-quadratic bumps, len 1.5K for K=4..64.
//
// R10 = R9 (stcs stores, bench 48.83) + R5's __launch_bounds__(256,7) (regs 32, 3.95 waves @ 98.8%,
// bench 48.74). The two wins are independent (L2 residency vs wave/occupancy shape) and measured
// separately from the same base; this composes them.

#define NB    128
#define LSEQ  32768
#define NFILT 17
#define TILE  1024
#define NTHR  256
#define NSV   1119          // valid xs elements = TILE + 95
#define NSX   1120

__device__ __forceinline__ float triWeightAbs(int t, int c) {
    // weight of quad filter t (t=0..4 <-> K=4,8,16,32,64) at absolute tap c (0..95); 0 outside support
    const int Ks[5] = {4, 8, 16, 32, 64};
    int K = Ks[t];
    int Lf = K + K / 2;
    int o = 47 - (Lf - 1) / 2;
    int j = c - o;
    if (j < 0 || j >= Lf) return 0.0f;
    int q = K / 4, half = K / 2;
    int s = j / half;
    int u = j - s * half;
    int num = (u < q) ? (u + 1) : (half - u);
    float b = (float)num / (float)q;        // exact: power-of-two denominator
    float w = b * b;
    return (s == 1) ? 2.0f * w : -w;
}

__global__ __launch_bounds__(NTHR, 7)
void Hybrid_block_64175401337035_kernel(const float* __restrict__ x,
                                        float* __restrict__ y) {
    __shared__ __align__(16) float xs[NSX];
    __shared__ __align__(16) float E[NSX];   // E[p] = (-1)^p * sum_{q<p} (-1)^q xs[q]; E[0]=0
    __shared__ float warpAgg[8];

    const int tid = threadIdx.x;
    const int n = blockIdx.y;
    const int tileStart = blockIdx.x * TILE;
    const float* xg = x + (size_t)n * LSEQ;

    // ---- load input tile (zero-padded at sequence edges); dense, conflict-free ----
    #pragma unroll
    for (int q = tid; q < NSX; q += NTHR) {
        int g = tileStart - 47 + q;
        xs[q] = (q < NSV && g >= 0 && g < LSEQ) ? xg[g] : 0.0f;
    }
    __syncthreads();

    // ---- block scan of (-1)^q xs[q], chunk=5/thread; stride-5 reads are conflict-free ----
    float loc[5];
    float run = 0.0f;
    const int qb = tid * 5;
    #pragma unroll
    for (int j = 0; j < 5; ++j) {
        int q = qb + j;
        float v = 0.0f;
        if (q < NSV) { v = xs[q]; if (q & 1) v = -v; }
        run += v;
        loc[j] = run;
    }
    const unsigned lane = tid & 31;
    const unsigned wid = tid >> 5;
    float inc = run;
    #pragma unroll
    for (int o = 1; o < 32; o <<= 1) {
        float nb = __shfl_up_sync(0xffffffffu, inc, o);
        if (lane >= (unsigned)o) inc += nb;
    }
    if (lane == 31) warpAgg[wid] = inc;
    __syncthreads();
    if (tid < 8) {
        float wv = warpAgg[tid];
        #pragma unroll
        for (int o = 1; o < 8; o <<= 1) {
            float nb = __shfl_up_sync(0xffu, wv, o);
            if (tid >= o) wv += nb;
        }
        warpAgg[tid] = wv;
    }
    __syncthreads();
    float pre = inc - run;
    if (wid > 0) pre += warpAgg[wid - 1];
    if (tid == 0) E[0] = 0.0f;
    #pragma unroll
    for (int j = 0; j < 5; ++j) {
        int q = qb + j;
        if (q < NSV) {
            float v = pre + loc[j];
            // E[q+1] = (-1)^(q+1) * A[q+1]:  q even -> negative
            E[q + 1] = (q & 1) ? v : -v;
        }
    }
    __syncthreads();

    const int xl0 = tid * 4;
    const int i0 = tileStart + xl0;
    float* ybase = y + (size_t)n * NFILT * LSEQ + i0;

    // ---- 12 alternating filters: s(a) = E[a+K]-E[a]; all windows served by 9 aligned LDS.128 ----
    const float4 e16 = *(const float4*)(E + xl0 + 16);
    const float4 e32 = *(const float4*)(E + xl0 + 32);
    const float4 e40 = *(const float4*)(E + xl0 + 40);
    const float4 e44 = *(const float4*)(E + xl0 + 44);
    const float4 e48 = *(const float4*)(E + xl0 + 48);
    const float4 e52 = *(const float4*)(E + xl0 + 52);
    const float4 e56 = *(const float4*)(E + xl0 + 56);
    const float4 e64 = *(const float4*)(E + xl0 + 64);
    const float4 e80 = *(const float4*)(E + xl0 + 80);

    {
        float w0[4], w1[4];
        #define EMIT(kkidx)                                                          \
        {                                                                            \
            float4 ye, yo;                                                           \
            ye.x = fmaxf(w0[0] - w1[0], 0.0f); yo.x = fmaxf(w1[0] - w0[0], 0.0f);    \
            ye.y = fmaxf(w0[1] - w1[1], 0.0f); yo.y = fmaxf(w1[1] - w0[1], 0.0f);    \
            ye.z = fmaxf(w0[2] - w1[2], 0.0f); yo.z = fmaxf(w1[2] - w0[2], 0.0f);    \
            ye.w = fmaxf(w0[3] - w1[3], 0.0f); yo.w = fmaxf(w1[3] - w0[3], 0.0f);    \
            __stcs((float4*)(ybase + (size_t)(kkidx) * LSEQ), ye);                   \
            __stcs((float4*)(ybase + (size_t)(6 + (kkidx)) * LSEQ), yo);             \
        }
        // K=2, o=47: W0 @47, W1 @49
        w0[0]=e44.w; w0[1]=e48.x; w0[2]=e48.y; w0[3]=e48.z;
        w1[0]=e48.y; w1[1]=e48.z; w1[2]=e48.w; w1[3]=e52.x;
        EMIT(0)
        // K=4, o=46: W0 @46, W1 @50
        w0[0]=e44.z; w0[1]=e44.w; w0[2]=e48.x; w0[3]=e48.y;
        w1[0]=e48.z; w1[1]=e48.w; w1[2]=e52.x; w1[3]=e52.y;
        EMIT(1)
        // K=8, o=44: W0 @44, W1 @52
        w0[0]=e44.x; w0[1]=e44.y; w0[2]=e44.z; w0[3]=e44.w;
        w1[0]=e52.x; w1[1]=e52.y; w1[2]=e52.z; w1[3]=e52.w;
        EMIT(2)
        // K=16, o=40: W0 @40, W1 @56
        w0[0]=e40.x; w0[1]=e40.y; w0[2]=e40.z; w0[3]=e40.w;
        w1[0]=e56.x; w1[1]=e56.y; w1[2]=e56.z; w1[3]=e56.w;
        EMIT(3)
        // K=32, o=32: W0 @32, W1 @64
        w0[0]=e32.x; w0[1]=e32.y; w0[2]=e32.z; w0[3]=e32.w;
        w1[0]=e64.x; w1[1]=e64.y; w1[2]=e64.z; w1[3]=e64.w;
        EMIT(4)
        // K=64, o=16: W0 @16, W1 @80
        w0[0]=e16.x; w0[1]=e16.y; w0[2]=e16.z; w0[3]=e16.w;
        w1[0]=e80.x; w1[1]=e80.y; w1[2]=e80.z; w1[3]=e80.w;
        EMIT(5)
        #undef EMIT
    }

    // ---- 5 quadratic filters: fully-unrolled sweep, FFMA-imm, dense LDS.128 ----
    float acc[5][4];
    #pragma unroll
    for (int t = 0; t < 5; ++t)
        #pragma unroll
        for (int pp = 0; pp < 4; ++pp) acc[t][pp] = 0.0f;

    float4 cur = *(const float4*)(xs + xl0);
    #pragma unroll
    for (int m = 0; m < 24; ++m) {
        float4 nxt = *(const float4*)(xs + xl0 + 4 * m + 4);
        float win[8] = {cur.x, cur.y, cur.z, cur.w, nxt.x, nxt.y, nxt.z, nxt.w};
        #pragma unroll
        for (int d = 0; d < 4; ++d) {
            const int c = 4 * m + d;
            #pragma unroll
            for (int t = 0; t < 5; ++t) {
                const float w = triWeightAbs(t, c);
                if (w != 0.0f) {
                    #pragma unroll
                    for (int pp = 0; pp < 4; ++pp)
                        acc[t][pp] = fmaf(w, win[d + pp], acc[t][pp]);
                }
            }
        }
        cur = nxt;
    }
    #pragma unroll
    for (int t = 0; t < 5; ++t) {
        float4 v;
        v.x = fmaxf(acc[t][0], 0.0f);
        v.y = fmaxf(acc[t][1], 0.0f);
        v.z = fmaxf(acc[t][2], 0.0f);
        v.w = fmaxf(acc[t][3], 0.0f);
        __stcs((float4*)(ybase + (size_t)(12 + t) * LSEQ), v);
    }
}

extern "C" void kernel_launch(void* const* d_in, const int* in_sizes, int n_in,
                              void* d_out, int out_size) {
    const float* x = (const float*)d_in[0];
    float* y = (float*)d_out;
    dim3 grid(LSEQ / TILE, NB);
    Hybrid_block_64175401337035_kernel<<<grid, NTHR>>>(x, y);
}